// round 10
// baseline (speedup 1.0000x reference)
#include <cuda_runtime.h>
#include <cstdint>
#include <cstddef>

// Problem constants
#define BB      2
#define CC      384
#define DD      32
#define HH      32
#define WW      32
#define HEADS   12
#define HD      32
#define WS      5
#define PADW    2
#define SSP     (DD*HH*WW)           // 32768
#define SCALE   0.17677669529663687f // 32^-0.5

// Scratch (device globals; allocation in kernel_launch is forbidden)
__device__ float g_qkv[(size_t)BB * 3 * CC * SSP];
__device__ float g_attn[(size_t)BB * CC * SSP];

// ---------------------------------------------------------------------------
// SGEMM: C[b][m][n] = sum_k A[m][k]*B[b][k][n] + bias[m]
// 128x128x16 tile, 256 threads, 8x8 microtile, LDG prefetch over compute.
// All dims divide evenly (M in {1152,384}, N=32768, K=384).
// ---------------------------------------------------------------------------
__global__ __launch_bounds__(256)
void sgemm128(const float* __restrict__ A, const float* __restrict__ B,
              const float* __restrict__ bias, float* __restrict__ C,
              int M, int N, int K, size_t strideB, size_t strideC)
{
    __shared__ __align__(16) float As[16][132];   // padded: 2-way store conflict max
    __shared__ __align__(16) float Bs[16][128];

    const float* Bp = B + (size_t)blockIdx.z * strideB;
    float*       Cp = C + (size_t)blockIdx.z * strideC;

    const int tid = threadIdx.x;
    const int tx  = tid & 15;
    const int ty  = tid >> 4;
    const int m0  = blockIdx.y * 128;
    const int n0  = blockIdx.x * 128;

    // A-load map: rows m0+ar and m0+ar+64, 4 k-floats at ak
    const int ar = tid >> 2;            // 0..63
    const int ak = (tid & 3) * 4;       // 0,4,8,12
    // B-load map: k-rows bk and bk+8, 4 n-floats at bn
    const int bk = tid >> 5;            // 0..7
    const int bn = (tid & 31) * 4;      // 0..124

    const float* Aptr0 = A + (size_t)(m0 + ar) * K + ak;
    const float* Aptr1 = A + (size_t)(m0 + ar + 64) * K + ak;
    const float* Bptr0 = Bp + (size_t)bk * N + n0 + bn;
    const float* Bptr1 = Bp + (size_t)(bk + 8) * N + n0 + bn;

    float acc[8][8];
#pragma unroll
    for (int i = 0; i < 8; i++)
#pragma unroll
        for (int j = 0; j < 8; j++) acc[i][j] = 0.f;

    float4 pa0 = *(const float4*)(Aptr0);
    float4 pa1 = *(const float4*)(Aptr1);
    float4 pb0 = *(const float4*)(Bptr0);
    float4 pb1 = *(const float4*)(Bptr1);

    for (int k0 = 0; k0 < K; k0 += 16) {
        As[ak + 0][ar]      = pa0.x;
        As[ak + 1][ar]      = pa0.y;
        As[ak + 2][ar]      = pa0.z;
        As[ak + 3][ar]      = pa0.w;
        As[ak + 0][ar + 64] = pa1.x;
        As[ak + 1][ar + 64] = pa1.y;
        As[ak + 2][ar + 64] = pa1.z;
        As[ak + 3][ar + 64] = pa1.w;
        *(float4*)&Bs[bk][bn]     = pb0;
        *(float4*)&Bs[bk + 8][bn] = pb1;
        __syncthreads();

        if (k0 + 16 < K) {          // prefetch next tile; overlaps compute
            pa0 = *(const float4*)(Aptr0 + k0 + 16);
            pa1 = *(const float4*)(Aptr1 + k0 + 16);
            pb0 = *(const float4*)(Bptr0 + (size_t)(k0 + 16) * N);
            pb1 = *(const float4*)(Bptr1 + (size_t)(k0 + 16) * N);
        }

#pragma unroll
        for (int kk = 0; kk < 16; kk++) {
            float a[8], b[8];
            *(float4*)&a[0] = *(const float4*)&As[kk][ty * 4];
            *(float4*)&a[4] = *(const float4*)&As[kk][ty * 4 + 64];
            *(float4*)&b[0] = *(const float4*)&Bs[kk][tx * 4];
            *(float4*)&b[4] = *(const float4*)&Bs[kk][tx * 4 + 64];
#pragma unroll
            for (int i = 0; i < 8; i++)
#pragma unroll
                for (int j = 0; j < 8; j++)
                    acc[i][j] = fmaf(a[i], b[j], acc[i][j]);
        }
        __syncthreads();
    }

#pragma unroll
    for (int i = 0; i < 8; i++) {
        const int mrow = m0 + ty * 4 + (i & 3) + (i >> 2) * 64;
        const float bv = bias[mrow];
        float4 o0, o1;
        o0.x = acc[i][0] + bv; o0.y = acc[i][1] + bv;
        o0.z = acc[i][2] + bv; o0.w = acc[i][3] + bv;
        o1.x = acc[i][4] + bv; o1.y = acc[i][5] + bv;
        o1.z = acc[i][6] + bv; o1.w = acc[i][7] + bv;
        *(float4*)(Cp + (size_t)mrow * N + n0 + tx * 4)      = o0;
        *(float4*)(Cp + (size_t)mrow * N + n0 + tx * 4 + 64) = o1;
    }
}

// ---------------------------------------------------------------------------
// Fused windowed attention. Grid (D, H/TY, B*HEADS), block 128 = 32(x)*4(y).
// Per dz: stage zero-padded k/v z-slice [HD][YH][XH] in smem; compute all 25
// (dy,dx) scores into registers, one online-softmax rescale per dz, then the
// 32-accumulator output phase.
// ---------------------------------------------------------------------------
#define TY       4
#define XH       36
#define YH       (TY + 2*PADW)        // 8
#define CH_EL    (YH*XH)              // 288
#define SLICE_EL (HD*CH_EL)           // 9216
#define PE_EL    (HD*WS*WS*WS)        // 4000
#define QSM_EL   (HD*128)             // 4096
#define ATTN_SMEM ((2*SLICE_EL + PE_EL + QSM_EL)*4)   // 106,944 B

__global__ __launch_bounds__(128)
void attn3d_kernel(const float* __restrict__ qkv,
                   const float* __restrict__ pos_embed,
                   float* __restrict__ attn_out)
{
    extern __shared__ float smem[];
    float* ksm = smem;                       // [HD][YH][XH]
    float* vsm = smem + SLICE_EL;
    float* pes = smem + 2 * SLICE_EL;        // [HD][125]
    float* qsm = smem + 2 * SLICE_EL + PE_EL; // [HD][128] per-thread column

    const int tid  = threadIdx.x;
    const int tx   = tid & 31;
    const int ty   = tid >> 5;
    const int z    = blockIdx.x;
    const int y0   = blockIdx.y * TY;
    const int bh   = blockIdx.z;
    const int b    = bh / HEADS;
    const int head = bh % HEADS;

    const float* qbase = qkv + ((size_t)b * (3 * CC) + head * HD) * SSP;
    const float* kbase = qbase + (size_t)CC * SSP;
    const float* vbase = qbase + (size_t)(2 * CC) * SSP;

    for (int i = tid; i < PE_EL; i += 128) pes[i] = pos_embed[i];

    const int y = y0 + ty;
    const size_t svox = (size_t)z * (HH * WW) + y * WW + tx;
#pragma unroll 8
    for (int hd = 0; hd < HD; hd++)
        qsm[hd * 128 + tid] = qbase[(size_t)hd * SSP + svox];

    // Staging geometry: this thread covers positions tid, tid+128, tid+256
    // of each 288-element channel slice. Precompute once.
    int g0, g1, g2;
    bool ib0, ib1, ib2;
    {
        int p  = tid;
        int yy = p / XH, xx = p - yy * XH;
        int ys = y0 + yy - PADW, xs = xx - PADW;
        ib0 = (ys >= 0) & (ys < HH) & (xs >= 0) & (xs < WW);
        g0  = ys * WW + xs;
        p  = tid + 128;
        yy = p / XH; xx = p - yy * XH;
        ys = y0 + yy - PADW; xs = xx - PADW;
        ib1 = (ys >= 0) & (ys < HH) & (xs >= 0) & (xs < WW);
        g1  = ys * WW + xs;
        p  = tid + 256;
        yy = p / XH; xx = p - yy * XH;
        ys = y0 + yy - PADW; xs = xx - PADW;
        ib2 = (p < CH_EL) & (ys >= 0) & (ys < HH) & (xs >= 0) & (xs < WW);
        g2  = ys * WW + xs;
    }
    const bool pv2 = (tid < CH_EL - 256);   // tid < 32

    float m = -1e30f, l = 0.f;
    float out[HD];
#pragma unroll
    for (int hd = 0; hd < HD; hd++) out[hd] = 0.f;

    const int base = ty * XH + tx;

    for (int dz = 0; dz < WS; dz++) {
        const int zs = z + dz - PADW;

        // ---- stage k/v slice ----
        if (zs >= 0 && zs < DD) {
            const float* kb = kbase + (size_t)zs * (HH * WW);
            const float* vb = vbase + (size_t)zs * (HH * WW);
#pragma unroll 4
            for (int ch = 0; ch < HD; ch++) {
                const ptrdiff_t co = (ptrdiff_t)ch * SSP;
                const int so = ch * CH_EL;
                ksm[so + tid]       = ib0 ? kb[co + g0] : 0.f;
                vsm[so + tid]       = ib0 ? vb[co + g0] : 0.f;
                ksm[so + tid + 128] = ib1 ? kb[co + g1] : 0.f;
                vsm[so + tid + 128] = ib1 ? vb[co + g1] : 0.f;
                if (pv2) {
                    ksm[so + tid + 256] = ib2 ? kb[co + g2] : 0.f;
                    vsm[so + tid + 256] = ib2 ? vb[co + g2] : 0.f;
                }
            }
        } else {
            for (int i = tid; i < SLICE_EL; i += 128) { ksm[i] = 0.f; vsm[i] = 0.f; }
        }
        __syncthreads();

        // ---- score phase: 25 independent accumulators ----
        float s[25];
#pragma unroll
        for (int j = 0; j < 25; j++) s[j] = 0.f;

        const float* peb = pes + dz * 25;
        for (int hd = 0; hd < HD; hd++) {
            const float  qh = qsm[hd * 128 + tid];
            const float* kr = ksm + hd * CH_EL + base;
            const float* pe = peb + hd * 125;           // broadcast reads
#pragma unroll
            for (int dy = 0; dy < 5; dy++)
#pragma unroll
                for (int dx = 0; dx < 5; dx++)
                    s[dy * 5 + dx] = fmaf(qh, kr[dy * XH + dx] + pe[dy * 5 + dx],
                                          s[dy * 5 + dx]);
        }

        // ---- online softmax (one rescale per dz) ----
        float mx = -1e30f;
#pragma unroll
        for (int j = 0; j < 25; j++) { s[j] *= SCALE; mx = fmaxf(mx, s[j]); }
        const float nm = fmaxf(m, mx);
        const float c  = __expf(m - nm);
        m = nm;
        l *= c;
#pragma unroll
        for (int hd = 0; hd < HD; hd++) out[hd] *= c;
        float ps = 0.f;
#pragma unroll
        for (int j = 0; j < 25; j++) { s[j] = __expf(s[j] - nm); ps += s[j]; }
        l += ps;

        // ---- output phase: 32 independent accumulators ----
        const float* vb2 = vsm + base;
#pragma unroll
        for (int dy = 0; dy < 5; dy++)
#pragma unroll
            for (int dx = 0; dx < 5; dx++) {
                const float  pj = s[dy * 5 + dx];
                const float* vr = vb2 + dy * XH + dx;
#pragma unroll
                for (int hd = 0; hd < HD; hd++)
                    out[hd] = fmaf(pj, vr[hd * CH_EL], out[hd]);
            }
        __syncthreads();
    }

    const float inv = 1.f / l;
    float* ob = attn_out + ((size_t)b * CC + head * HD) * SSP + svox;
#pragma unroll
    for (int hd = 0; hd < HD; hd++) ob[(size_t)hd * SSP] = out[hd] * inv;
}

// ---------------------------------------------------------------------------
// Launch
// ---------------------------------------------------------------------------
extern "C" void kernel_launch(void* const* d_in, const int* in_sizes, int n_in,
                              void* d_out, int out_size)
{
    const float* x         = (const float*)d_in[0];
    const float* w_qkv     = (const float*)d_in[1];
    const float* b_qkv     = (const float*)d_in[2];
    const float* w_proj    = (const float*)d_in[3];
    const float* b_proj    = (const float*)d_in[4];
    const float* pos_embed = (const float*)d_in[5];
    float* outp = (float*)d_out;

    float* qkv;  cudaGetSymbolAddress((void**)&qkv,  g_qkv);
    float* attn; cudaGetSymbolAddress((void**)&attn, g_attn);

    // 1) QKV projection: M=1152, N=32768, K=384, batch 2
    {
        dim3 grid(SSP / 128, (3 * CC) / 128, BB);
        sgemm128<<<grid, 256>>>(w_qkv, x, b_qkv, qkv,
                                3 * CC, SSP, CC,
                                (size_t)CC * SSP, (size_t)(3 * CC) * SSP);
    }

    // 2) Fused windowed attention
    {
        cudaFuncSetAttribute(attn3d_kernel,
                             cudaFuncAttributeMaxDynamicSharedMemorySize,
                             ATTN_SMEM);
        dim3 grid(DD, HH / TY, BB * HEADS);
        attn3d_kernel<<<grid, 128, ATTN_SMEM>>>(qkv, pos_embed, attn);
    }

    // 3) Output projection: M=384, N=32768, K=384, batch 2
    {
        dim3 grid(SSP / 128, CC / 128, BB);
        sgemm128<<<grid, 256>>>(w_proj, attn, b_proj, outp,
                                CC, SSP, CC,
                                (size_t)CC * SSP, (size_t)CC * SSP);
    }
}

// round 13
// speedup vs baseline: 1.4432x; 1.4432x over previous
#include <cuda_runtime.h>
#include <cuda_bf16.h>
#include <cstdint>
#include <cstddef>

// Problem constants
#define BB      2
#define CC      384
#define DD      32
#define HH      32
#define WW      32
#define HEADS   12
#define HD      32
#define WS      5
#define PADW    2
#define SSP     (DD*HH*WW)           // 32768
#define SCALE   0.17677669529663687f // 32^-0.5

// Scratch (device globals; allocation in kernel_launch is forbidden)
__device__ float g_qkv[(size_t)BB * 3 * CC * SSP];
__device__ float g_attn[(size_t)BB * CC * SSP];
__device__ __nv_bfloat16 g_Ahi[(size_t)3 * CC * CC];
__device__ __nv_bfloat16 g_Alo[(size_t)3 * CC * CC];
__device__ __nv_bfloat16 g_Bhi[(size_t)BB * SSP * CC];
__device__ __nv_bfloat16 g_Blo[(size_t)BB * SSP * CC];

// ===========================================================================
// Warp-MMA helpers (base sm_103-legal PTX: ldmatrix + mma.sync bf16)
// ===========================================================================
__device__ __forceinline__ uint32_t smem_u32(const void* p) {
    uint32_t a;
    asm("{ .reg .u64 t; cvta.to.shared.u64 t, %1; cvt.u32.u64 %0, t; }"
        : "=r"(a) : "l"(p));
    return a;
}
__device__ __forceinline__ void ldsm4(uint32_t* r, uint32_t addr) {
    asm volatile("ldmatrix.sync.aligned.m8n8.x4.shared.b16 {%0,%1,%2,%3}, [%4];"
                 : "=r"(r[0]), "=r"(r[1]), "=r"(r[2]), "=r"(r[3]) : "r"(addr));
}
__device__ __forceinline__ void mma16816(float* d, const uint32_t* a, const uint32_t* b) {
    asm volatile("mma.sync.aligned.m16n8k16.row.col.f32.bf16.bf16.f32 "
                 "{%0,%1,%2,%3}, {%4,%5,%6,%7}, {%8,%9}, {%0,%1,%2,%3};"
                 : "+f"(d[0]), "+f"(d[1]), "+f"(d[2]), "+f"(d[3])
                 : "r"(a[0]), "r"(a[1]), "r"(a[2]), "r"(a[3]),
                   "r"(b[0]), "r"(b[1]));
}

// ===========================================================================
// Precision-split conversion kernels (unchanged from R10 — verified path)
// ===========================================================================
__global__ __launch_bounds__(256)
void split_kernel(const float* __restrict__ in, __nv_bfloat16* __restrict__ hi,
                  __nv_bfloat16* __restrict__ lo, int n)
{
    int i = blockIdx.x * 256 + threadIdx.x;
    if (i < n) {
        float v = in[i];
        __nv_bfloat16 h = __float2bfloat16(v);
        hi[i] = h;
        lo[i] = __float2bfloat16(v - __bfloat162float(h));
    }
}

// in[b][k][n] fp32 -> hi/lo[b][n][k] bf16 (transpose + split)
__global__ __launch_bounds__(256)
void transpose_split_kernel(const float* __restrict__ in,
                            __nv_bfloat16* __restrict__ hi,
                            __nv_bfloat16* __restrict__ lo, int K, int N)
{
    __shared__ float tile[32][33];
    const float* inp = in + (size_t)blockIdx.z * K * N;
    __nv_bfloat16* hip = hi + (size_t)blockIdx.z * N * K;
    __nv_bfloat16* lop = lo + (size_t)blockIdx.z * N * K;
    const int tx = threadIdx.x, ty = threadIdx.y;
    const int n = blockIdx.x * 32 + tx;
    const int k0 = blockIdx.y * 32;
#pragma unroll
    for (int j = 0; j < 32; j += 8)
        tile[ty + j][tx] = inp[(size_t)(k0 + ty + j) * N + n];
    __syncthreads();
    const int n2 = blockIdx.x * 32 + ty;
    const int k = k0 + tx;
#pragma unroll
    for (int j = 0; j < 32; j += 8) {
        float v = tile[tx][ty + j];
        __nv_bfloat16 h = __float2bfloat16(v);
        hip[(size_t)(n2 + j) * K + k] = h;
        lop[(size_t)(n2 + j) * K + k] = __float2bfloat16(v - __bfloat162float(h));
    }
}

// ===========================================================================
// Split-bf16 GEMM via mma.sync: C[b][m][n] = sum_k A[m][k]*B[b][n][k] + bias[m]
// CTA: 128x128 C tile, 256 thr = 8 warps (2M x 4N), 64x32 per warp.
// K chunks of 32; smem rows padded to 80B (ldmatrix conflict-free).
// 3 MMAs per (tile,k16): hi*hi + hi*lo + lo*hi.
// ===========================================================================
#define KC         32
#define SROW       80                    // bytes per smem row (32 bf16 + pad)
#define TILE_BYTES (128 * SROW)          // 10240

__global__ __launch_bounds__(256)
void gemm_mma(const __nv_bfloat16* __restrict__ Ahi, const __nv_bfloat16* __restrict__ Alo,
              const __nv_bfloat16* __restrict__ Bhi, const __nv_bfloat16* __restrict__ Blo,
              const float* __restrict__ bias, float* __restrict__ C,
              int M, int N)
{
    __shared__ __align__(16) char smT[4 * TILE_BYTES];   // Ahi | Alo | Bhi | Blo
    const uint32_t sb = smem_u32(smT);

    const int tid  = threadIdx.x;
    const int lane = tid & 31;
    const int wid  = tid >> 5;
    const int wm   = wid >> 2;            // 0..1
    const int wn   = wid & 3;             // 0..3
    const int m0   = blockIdx.y * 128;
    const int n0   = blockIdx.x * 128;

    const char* gAh = (const char*)(Ahi + (size_t)m0 * CC);
    const char* gAl = (const char*)(Alo + (size_t)m0 * CC);
    const char* gBh = (const char*)(Bhi + (size_t)blockIdx.z * N * CC + (size_t)n0 * CC);
    const char* gBl = (const char*)(Blo + (size_t)blockIdx.z * N * CC + (size_t)n0 * CC);

    // Loader map: thread -> (row, 32B half of the 64B k-chunk row)
    const int lr = tid >> 1;
    const int lc = (tid & 1) * 32;
    const size_t goff = (size_t)lr * (CC * 2) + lc;
    const int    soff = lr * SROW + lc;

    float acc[4][4][4];
#pragma unroll
    for (int i = 0; i < 4; i++)
#pragma unroll
        for (int j = 0; j < 4; j++)
#pragma unroll
            for (int q = 0; q < 4; q++) acc[i][j][q] = 0.f;

    // ldmatrix source addresses (fixed per thread; +k-step byte offsets)
    const int arow = wm * 64 + (lane & 15);
    const int acol = (lane >> 4) * 16;                       // bytes
    const int brow = wn * 32 + ((lane >> 4) << 3) + (lane & 7);
    const int bcol = ((lane >> 3) & 1) * 16;                 // bytes

    for (int c = 0; c < CC / KC; c++) {
        const int kb = c * KC * 2;       // byte offset along K
        {
            const char* sA0 = gAh + kb + goff;
            const char* sA1 = gAl + kb + goff;
            const char* sB0 = gBh + kb + goff;
            const char* sB1 = gBl + kb + goff;
            char* d = smT + soff;
            *(uint4*)(d + 0 * TILE_BYTES)      = *(const uint4*)(sA0);
            *(uint4*)(d + 0 * TILE_BYTES + 16) = *(const uint4*)(sA0 + 16);
            *(uint4*)(d + 1 * TILE_BYTES)      = *(const uint4*)(sA1);
            *(uint4*)(d + 1 * TILE_BYTES + 16) = *(const uint4*)(sA1 + 16);
            *(uint4*)(d + 2 * TILE_BYTES)      = *(const uint4*)(sB0);
            *(uint4*)(d + 2 * TILE_BYTES + 16) = *(const uint4*)(sB0 + 16);
            *(uint4*)(d + 3 * TILE_BYTES)      = *(const uint4*)(sB1);
            *(uint4*)(d + 3 * TILE_BYTES + 16) = *(const uint4*)(sB1 + 16);
        }
        __syncthreads();

#pragma unroll
        for (int ks = 0; ks < 2; ks++) {
            const int kso = ks * 32;     // 16 k-elements = 32 bytes
            uint32_t ah[4][4], al[4][4];
#pragma unroll
            for (int i = 0; i < 4; i++) {
                const uint32_t ad = sb + (arow + i * 16) * SROW + acol + kso;
                ldsm4(ah[i], ad);
                ldsm4(al[i], ad + TILE_BYTES);
            }
#pragma unroll
            for (int p = 0; p < 2; p++) {
                const uint32_t bd = sb + 2 * TILE_BYTES
                                  + (brow + p * 16) * SROW + bcol + kso;
                uint32_t bh[4], bl[4];
                ldsm4(bh, bd);
                ldsm4(bl, bd + TILE_BYTES);
#pragma unroll
                for (int i = 0; i < 4; i++) {
                    mma16816(acc[i][2 * p + 0], ah[i], bh + 0);
                    mma16816(acc[i][2 * p + 0], ah[i], bl + 0);
                    mma16816(acc[i][2 * p + 0], al[i], bh + 0);
                    mma16816(acc[i][2 * p + 1], ah[i], bh + 2);
                    mma16816(acc[i][2 * p + 1], ah[i], bl + 2);
                    mma16816(acc[i][2 * p + 1], al[i], bh + 2);
                }
            }
        }
        __syncthreads();
    }

    // Epilogue: direct GMEM stores (float2), bias added
    float* Cp = C + (size_t)blockIdx.z * M * N;
#pragma unroll
    for (int i = 0; i < 4; i++) {
        const int r0 = m0 + wm * 64 + i * 16 + (lane >> 2);
        const int r1 = r0 + 8;
        const float bv0 = bias[r0];
        const float bv1 = bias[r1];
#pragma unroll
        for (int j = 0; j < 4; j++) {
            const int cc0 = n0 + wn * 32 + j * 8 + (lane & 3) * 2;
            float2 v0, v1;
            v0.x = acc[i][j][0] + bv0; v0.y = acc[i][j][1] + bv0;
            v1.x = acc[i][j][2] + bv1; v1.y = acc[i][j][3] + bv1;
            *(float2*)(Cp + (size_t)r0 * N + cc0) = v0;
            *(float2*)(Cp + (size_t)r1 * N + cc0) = v1;
        }
    }
}

// ===========================================================================
// Fused windowed attention — R3/R4 version (branchy online softmax; the
// faster of the two measured variants)
// ===========================================================================
#define TY       4
#define XH       36
#define YH       (TY + 2*PADW)
#define SLICE_EL (HD * YH * XH)
#define PE_EL    (HD * WS * WS * WS)
#define ATTN_SMEM_BYTES ((2 * SLICE_EL + PE_EL) * 4)

__global__ __launch_bounds__(128)
void attn3d_kernel(const float* __restrict__ qkv,
                   const float* __restrict__ pos_embed,
                   float* __restrict__ attn_out)
{
    extern __shared__ float smem[];
    float* ksm = smem;
    float* vsm = smem + SLICE_EL;
    float* pes = smem + 2 * SLICE_EL;

    const int tid  = threadIdx.x;
    const int tx   = tid & 31;
    const int ty   = tid >> 5;
    const int z    = blockIdx.x;
    const int y0   = blockIdx.y * TY;
    const int bh   = blockIdx.z;
    const int b    = bh / HEADS;
    const int head = bh % HEADS;

    const int y = y0 + ty;
    const int x = tx;

    const float* qbase = qkv + ((size_t)b * (3 * CC) + head * HD) * SSP;
    const float* kbase = qbase + (size_t)CC * SSP;
    const float* vbase = qbase + (size_t)(2 * CC) * SSP;

    for (int i = tid; i < PE_EL; i += 128) pes[i] = pos_embed[i];

    const size_t svox = (size_t)z * (HH * WW) + y * WW + x;
    float qreg[HD];
#pragma unroll
    for (int hd = 0; hd < HD; hd++) qreg[hd] = qbase[(size_t)hd * SSP + svox];

    float m = -1e30f;
    float l = 0.f;
    float out[HD];
#pragma unroll
    for (int hd = 0; hd < HD; hd++) out[hd] = 0.f;

    for (int dz = 0; dz < WS; dz++) {
        const int zs = z + dz - PADW;
        const bool zin = (zs >= 0) && (zs < DD);
        for (int idx = tid; idx < SLICE_EL; idx += 128) {
            const int ch = idx / (YH * XH);
            const int r  = idx - ch * (YH * XH);
            const int yy = r / XH;
            const int xx = r - yy * XH;
            const int ys = y0 + yy - PADW;
            const int xs = xx - PADW;
            float kv = 0.f, vv = 0.f;
            if (zin && ys >= 0 && ys < HH && xs >= 0 && xs < WW) {
                const size_t g = (size_t)ch * SSP + (size_t)zs * (HH * WW) + ys * WW + xs;
                kv = kbase[g];
                vv = vbase[g];
            }
            ksm[idx] = kv;
            vsm[idx] = vv;
        }
        __syncthreads();

        for (int dy = 0; dy < WS; dy++) {
            for (int dx = 0; dx < WS; dx++) {
                const int off  = (dz * WS + dy) * WS + dx;
                const int sidx = (ty + dy) * XH + tx + dx;
                float s = 0.f;
#pragma unroll
                for (int hd = 0; hd < HD; hd++)
                    s = fmaf(qreg[hd], ksm[hd * (YH * XH) + sidx] + pes[hd * 125 + off], s);
                s *= SCALE;

                if (s > m) {
                    const float c = __expf(m - s);
                    m = s;
                    l = l * c + 1.f;
#pragma unroll
                    for (int hd = 0; hd < HD; hd++)
                        out[hd] = out[hd] * c + vsm[hd * (YH * XH) + sidx];
                } else {
                    const float p = __expf(s - m);
                    l += p;
#pragma unroll
                    for (int hd = 0; hd < HD; hd++)
                        out[hd] = fmaf(p, vsm[hd * (YH * XH) + sidx], out[hd]);
                }
            }
        }
        __syncthreads();
    }

    const float inv = 1.f / l;
    float* obase = attn_out + ((size_t)b * CC + head * HD) * SSP + svox;
#pragma unroll
    for (int hd = 0; hd < HD; hd++) obase[(size_t)hd * SSP] = out[hd] * inv;
}

// ===========================================================================
// Launch
// ===========================================================================
extern "C" void kernel_launch(void* const* d_in, const int* in_sizes, int n_in,
                              void* d_out, int out_size)
{
    const float* x         = (const float*)d_in[0];
    const float* w_qkv     = (const float*)d_in[1];
    const float* b_qkv     = (const float*)d_in[2];
    const float* w_proj    = (const float*)d_in[3];
    const float* b_proj    = (const float*)d_in[4];
    const float* pos_embed = (const float*)d_in[5];
    float* outp = (float*)d_out;

    float* qkv;  cudaGetSymbolAddress((void**)&qkv,  g_qkv);
    float* attn; cudaGetSymbolAddress((void**)&attn, g_attn);
    __nv_bfloat16 *Ahi, *Alo, *Bhi, *Blo;
    cudaGetSymbolAddress((void**)&Ahi, g_Ahi);
    cudaGetSymbolAddress((void**)&Alo, g_Alo);
    cudaGetSymbolAddress((void**)&Bhi, g_Bhi);
    cudaGetSymbolAddress((void**)&Blo, g_Blo);

    cudaFuncSetAttribute(attn3d_kernel,
                         cudaFuncAttributeMaxDynamicSharedMemorySize,
                         ATTN_SMEM_BYTES);

    // 1) Split w_qkv; transpose+split x
    {
        const int nA = 3 * CC * CC;
        split_kernel<<<(nA + 255) / 256, 256>>>(w_qkv, Ahi, Alo, nA);
        dim3 g(SSP / 32, CC / 32, BB);
        transpose_split_kernel<<<g, dim3(32, 8)>>>(x, Bhi, Blo, CC, SSP);
    }
    // 2) QKV projection (HMMA): M=1152, N=32768
    {
        dim3 g(SSP / 128, (3 * CC) / 128, BB);
        gemm_mma<<<g, 256>>>(Ahi, Alo, Bhi, Blo, b_qkv, qkv, 3 * CC, SSP);
    }
    // 3) Fused windowed attention
    {
        dim3 g(DD, HH / TY, BB * HEADS);
        attn3d_kernel<<<g, 128, ATTN_SMEM_BYTES>>>(qkv, pos_embed, attn);
    }
    // 4) Split w_proj; transpose+split attention output
    {
        const int nA = CC * CC;
        split_kernel<<<(nA + 255) / 256, 256>>>(w_proj, Ahi, Alo, nA);
        dim3 g(SSP / 32, CC / 32, BB);
        transpose_split_kernel<<<g, dim3(32, 8)>>>(attn, Bhi, Blo, CC, SSP);
    }
    // 5) Output projection (HMMA): M=384, N=32768
    {
        dim3 g(SSP / 128, CC / 128, BB);
        gemm_mma<<<g, 256>>>(Ahi, Alo, Bhi, Blo, b_proj, outp, CC, SSP);
    }
}